// round 14
// baseline (speedup 1.0000x reference)
#include <cuda_runtime.h>

#define B_TOT   16384
#define TM      16
#define NTHR    384

typedef unsigned long long u64;

__device__ __forceinline__ u64 pk2(float lo, float hi) {
    u64 r; asm("mov.b64 %0,{%1,%2};" : "=l"(r) : "f"(lo), "f"(hi)); return r;
}
__device__ __forceinline__ float2 upk2(u64 v) {
    float2 f; asm("mov.b64 {%0,%1},%2;" : "=f"(f.x), "=f"(f.y) : "l"(v)); return f;
}
__device__ __forceinline__ void fma2(u64& d, u64 a, u64 b) {
    asm("fma.rn.f32x2 %0,%1,%2,%0;" : "+l"(d) : "l"(a), "l"(b));
}
__device__ __forceinline__ void add2(u64& d, u64 a) {
    asm("add.rn.f32x2 %0,%0,%1;" : "+l"(d) : "l"(a));
}
// pack two f32 -> bf16x2 (hi<<16 | lo)
__device__ __forceinline__ unsigned cvtb2(float hi, float lo) {
    unsigned r; asm("cvt.rn.bf16x2.f32 %0,%1,%2;" : "=r"(r) : "f"(hi), "f"(lo)); return r;
}
// unpack bf16x2 -> f32x2  (f32 = bf16 << 16)
__device__ __forceinline__ u64 bup(unsigned v) {
    unsigned lo = v << 16, hi = v & 0xFFFF0000u;
    u64 r; asm("mov.b64 %0,{%1,%2};" : "=l"(r) : "r"(lo), "r"(hi)); return r;
}

// Shared layout (floats):
//   [0,36864)        shW2   192x192 fp32
//   [36864,40704)    shAct  192x20  rows: 4 groups x uint4{a01,a23,d01,d23} bf16x2
//   [40704,43776)    shW1a  16x192
//   [43776,46848)    shW3t  16x192
//   [46848,46864)    shB3   16
//   [46864,...)      ALIAS P: prologue hS 256x16 (4096) overlays:
//     P+0     shA2t  16x196 (3136)
//     P+3136  shFJ3  3x(16x17) (816)
//     P+3952  shTW   12x4 (48)
//     P+4000  shTR   16
//     P+4016  shYE   16x36 (576)
#define SMEM_FLOATS 51456

__global__ __launch_bounds__(NTHR, 1)
void ConditionalCNF_27590869910221_kernel(
    const float* __restrict__ theta, const float* __restrict__ hg,
    const float* __restrict__ eps,   const float* __restrict__ W1,
    const float* __restrict__ b1,    const float* __restrict__ W2,
    const float* __restrict__ b2,    const float* __restrict__ W3,
    const float* __restrict__ b3,    float* __restrict__ out)
{
    extern __shared__ float sm[];
    float* shW2  = sm;
    float* shAct = sm + 36864;
    float* shW1a = sm + 40704;
    float* shW3t = sm + 43776;
    float* shB3  = sm + 46848;
    float* hP    = sm + 46864;          // prologue alias base
    float* shA2t = sm + 46864;
    float* shFJ3 = sm + 50000;
    float* shTW  = sm + 50816;
    float* shTR  = sm + 50864;
    float* shYE  = sm + 50880;

    const int tid = threadIdx.x;
    const int u = tid % 96;          // column-pair index
    const int g = tid / 96;          // sample quartet (0..3)
    const int wid = tid >> 5;        // warp id (uniform g per warp)
    const int lane = tid & 31;
    const int j0 = 2 * u;
    const int sb = 4 * g;            // sample base within tile
    const int s0 = blockIdx.x * TM;
    const float dtf = -0.1f;
    const int es = tid >> 4, ed = tid & 15;   // slot (sample, dim) for tid<256

    // per-thread constants
    const float2 w1tReg = *(const float2*)(W1 + 272 * 192 + j0);
    const float2 b2Reg  = *(const float2*)(b2 + j0);

    // ---------------- phase 0: stage weights / state ----------------
    float yReg = 0.f, fb1 = 0.f, fb2 = 0.f, fb3 = 0.f, epsReg = 0.f;
    {
        const float4* W2g4 = (const float4*)W2;
        float4* shW24 = (float4*)shW2;
        for (int i = tid; i < 36864 / 4; i += NTHR) shW24[i] = W2g4[i];
        for (int i = tid; i < 3072; i += NTHR) shW1a[i] = W1[i];           // rows 0..15
        for (int i = tid; i < 3072; i += NTHR) {                           // W3 transpose
            int k = i >> 4, dd = i & 15;
            shW3t[dd * 192 + k] = W3[i];
        }
        if (tid < 16) shB3[tid] = b3[tid];
        if (tid < 256) {
            yReg = theta[s0 * 16 + tid];
            epsReg = eps[(0 * B_TOT + s0 + es) * 16 + ed];
        }
        // h tile into hP as hS[c][s], row stride 16 (prologue alias)
        const float4* hg4 = (const float4*)hg;
        for (int i = tid; i < 1024; i += NTHR) {
            float4 v = hg4[s0 * 64 + i];
            int s = i >> 6, c = (i & 63) * 4;
            hP[(c + 0) * 16 + s] = v.x; hP[(c + 1) * 16 + s] = v.y;
            hP[(c + 2) * 16 + s] = v.z; hP[(c + 3) * 16 + s] = v.w;
        }
    }
    __syncthreads();

    // ------------- hc = b1 + h @ W1[16:272,:] (register resident) -------------
    u64 hcReg[2][2];
    {
        float2 bj = *(const float2*)(b1 + j0);
        hcReg[0][0] = hcReg[0][1] = pk2(bj.x, bj.x);
        hcReg[1][0] = hcReg[1][1] = pk2(bj.y, bj.y);
        const float* hrow = hP + sb;
        #pragma unroll 4
        for (int k = 0; k < 256; k++) {
            float2 w = *(const float2*)(W1 + (16 + k) * 192 + j0);         // L2-resident LDG
            u64 w0 = pk2(w.x, w.x), w1 = pk2(w.y, w.y);
            ulonglong2 A0 = *(const ulonglong2*)(hrow + k * 16);
            fma2(hcReg[0][0], A0.x, w0); fma2(hcReg[0][1], A0.y, w0);
            fma2(hcReg[1][0], A0.x, w1); fma2(hcReg[1][1], A0.y, w1);
        }
    }
    __syncthreads();   // all hS reads done; alias region reusable

    // shYE init for stage 0 (y = theta, eps[0]); prefetch eps[1]; shTR zero
    if (tid < 256) {
        shYE[ed * 36 + es] = yReg;
        shYE[ed * 36 + 16 + es] = epsReg;
        epsReg = eps[(1 * B_TOT + s0 + es) * 16 + ed];
    }
    if (tid < 16) shTR[tid] = 0.f;
    __syncthreads();   // shYE(0) ready

    const float kSQ = 0.70710678118654752f;    // 1/sqrt(2)
    const float kPDF = 0.3989422804014327f;    // 1/sqrt(2*pi)

    u64 aA[2][2], aD[2][2], aW[2][2];

    for (int idx = 0; idx < 40; idx++) {
        int st = idx & 3;
        float t0 = 1.0f + dtf * (float)(idx >> 2);
        float tc = t0 + dtf * (st == 0 ? 0.f : st == 1 ? (1.f / 3.f)
                             : st == 2 ? (2.f / 3.f) : 1.f);

        // ---- layer 1: z1 = hc + t*W1t + y@W1a ; dz1 = e@W1a ; we = W3.e ----
        {
            u64 tw0 = pk2(tc * w1tReg.x, tc * w1tReg.x);
            u64 tw1 = pk2(tc * w1tReg.y, tc * w1tReg.y);
            #pragma unroll
            for (int p = 0; p < 2; p++) {
                aA[0][p] = hcReg[0][p]; add2(aA[0][p], tw0);
                aA[1][p] = hcReg[1][p]; add2(aA[1][p], tw1);
                aD[0][p] = aD[1][p] = 0ull;
                aW[0][p] = aW[1][p] = 0ull;
            }
        }
        #pragma unroll
        for (int k = 0; k < 16; k++) {
            const float* ar = shYE + k * 36 + sb;
            ulonglong2 A0 = *(const ulonglong2*)ar;
            ulonglong2 E0 = *(const ulonglong2*)(ar + 16);
            float2 w  = *(const float2*)(shW1a + k * 192 + j0);
            float2 w3 = *(const float2*)(shW3t + k * 192 + j0);
            u64 w0 = pk2(w.x, w.x), w1 = pk2(w.y, w.y);
            u64 v0 = pk2(w3.x, w3.x), v1 = pk2(w3.y, w3.y);
            fma2(aA[0][0], A0.x, w0); fma2(aA[0][1], A0.y, w0);
            fma2(aA[1][0], A0.x, w1); fma2(aA[1][1], A0.y, w1);
            fma2(aD[0][0], E0.x, w0); fma2(aD[0][1], E0.y, w0);
            fma2(aD[1][0], E0.x, w1); fma2(aD[1][1], E0.y, w1);
            fma2(aW[0][0], E0.x, v0); fma2(aW[0][1], E0.y, v0);
            fma2(aW[1][0], E0.x, v1); fma2(aW[1][1], E0.y, v1);
        }

        // GELU layer1 + store a1/d1 packed bf16: uint4{a01,a23,d01,d23}
        #pragma unroll
        for (int jj = 0; jj < 2; jj++) {
            float va[4], vd[4];
            #pragma unroll
            for (int p = 0; p < 2; p++) {
                float2 z  = upk2(aA[jj][p]);
                float2 dz = upk2(aD[jj][p]);
                float c0 = 0.5f * (1.f + erff(z.x * kSQ));
                float c1 = 0.5f * (1.f + erff(z.y * kSQ));
                va[2 * p]     = z.x * c0;
                va[2 * p + 1] = z.y * c1;
                float g0 = c0 + z.x * kPDF * __expf(-0.5f * z.x * z.x);
                float g1 = c1 + z.y * kPDF * __expf(-0.5f * z.y * z.y);
                vd[2 * p]     = g0 * dz.x;
                vd[2 * p + 1] = g1 * dz.y;
            }
            uint4 pkd;
            pkd.x = cvtb2(va[1], va[0]); pkd.y = cvtb2(va[3], va[2]);
            pkd.z = cvtb2(vd[1], vd[0]); pkd.w = cvtb2(vd[3], vd[2]);
            *(uint4*)(shAct + (j0 + jj) * 20 + sb) = pkd;
        }
        __syncthreads();   // B: act rows ready

        // ---- layer 2: z2 = a1@W2 + b2 ; dz2 = d1@W2 (bf16 acts, fp32 weights) ----
        #pragma unroll
        for (int p = 0; p < 2; p++) {
            aA[0][p] = pk2(b2Reg.x, b2Reg.x);
            aA[1][p] = pk2(b2Reg.y, b2Reg.y);
            aD[0][p] = aD[1][p] = 0ull;
        }
        #pragma unroll 8
        for (int k = 0; k < 192; k++) {
            uint4 q = *(const uint4*)(shAct + k * 20 + sb);
            float2 w = *(const float2*)(shW2 + k * 192 + j0);
            u64 w0 = pk2(w.x, w.x), w1 = pk2(w.y, w.y);
            u64 A0 = bup(q.x), A1 = bup(q.y);
            u64 E0 = bup(q.z), E1 = bup(q.w);
            fma2(aA[0][0], A0, w0); fma2(aA[0][1], A1, w0);
            fma2(aA[1][0], A0, w1); fma2(aA[1][1], A1, w1);
            fma2(aD[0][0], E0, w0); fma2(aD[0][1], E1, w0);
            fma2(aD[1][0], E0, w1); fma2(aD[1][1], E1, w1);
        }

        // GELU layer2: a2 -> shA2t fp32 (own region); trace partial in regs
        float tp[4] = {0.f, 0.f, 0.f, 0.f};
        #pragma unroll
        for (int jj = 0; jj < 2; jj++) {
            #pragma unroll
            for (int p = 0; p < 2; p++) {
                float2 z  = upk2(aA[jj][p]);
                float2 dz = upk2(aD[jj][p]);
                float c0 = 0.5f * (1.f + erff(z.x * kSQ));
                float c1 = 0.5f * (1.f + erff(z.y * kSQ));
                float a0 = z.x * c0, a1v = z.y * c1;
                float g0 = c0 + z.x * kPDF * __expf(-0.5f * z.x * z.x);
                float g1 = c1 + z.y * kPDF * __expf(-0.5f * z.y * z.y);
                float d0 = g0 * dz.x, d1v = g1 * dz.y;
                int ca = sb + 2 * p;
                shA2t[(ca)     * 196 + j0 + jj] = a0;
                shA2t[(ca + 1) * 196 + j0 + jj] = a1v;
                float2 wv = upk2(aW[jj][p]);
                tp[2 * p]     += d0  * wv.x;     // d2 . (W3 e)
                tp[2 * p + 1] += d1v * wv.y;
            }
        }
        // warp butterfly reduce (warp uniform in g)
        #pragma unroll
        for (int off = 16; off > 0; off >>= 1) {
            #pragma unroll
            for (int i = 0; i < 4; i++)
                tp[i] += __shfl_xor_sync(0xFFFFFFFFu, tp[i], off);
        }
        if (lane == 0) {
            #pragma unroll
            for (int i = 0; i < 4; i++) shTW[wid * 4 + i] = tp[i];
        }
        __syncthreads();   // D: a2t + shTW ready

        // ---- layer 3: f = a2 @ W3, 3-way K-split, 768 microtasks over 384 thr ----
        #pragma unroll
        for (int r = 0; r < 2; r++) {
            int m = tid + 384 * r;
            int third = m >> 8, o = m & 255;
            int s = o & 15, dd = o >> 4;
            const float* ap = shA2t + s * 196 + third * 64;
            const float* wp = shW3t + dd * 192 + third * 64;
            float acc = 0.f;
            #pragma unroll 8
            for (int k = 0; k < 64; k += 4) {
                float4 av = *(const float4*)(ap + k);
                float4 wv = *(const float4*)(wp + k);
                acc += av.x * wv.x + av.y * wv.y + av.z * wv.z + av.w * wv.w;
            }
            shFJ3[third * 272 + s * 17 + dd] = acc;
        }
        __syncthreads();   // E: shFJ3 ready

        // ---- fused epilogue + next-stage staging ----
        if (tid < 256) {
            float f = shFJ3[es * 17 + ed] + shFJ3[272 + es * 17 + ed]
                    + shFJ3[544 + es * 17 + ed] + shB3[ed];
            float yc;
            if      (st == 0) { fb1 = f; yc = yReg + (dtf * (1.f / 3.f)) * fb1; }
            else if (st == 1) { fb2 = f; yc = yReg + dtf * (fb2 - (1.f / 3.f) * fb1); }
            else if (st == 2) { fb3 = f; yc = yReg + dtf * (fb1 - fb2 + fb3); }
            else { yReg += dtf * 0.125f * (fb1 + 3.f * (fb2 + fb3) + f); yc = yReg; }
            if (idx < 39) {
                shYE[ed * 36 + es] = yc;
                shYE[ed * 36 + 16 + es] = epsReg;       // eps for stage idx+1
                int nxt = idx + 2; if (nxt > 39) nxt = 39;
                epsReg = eps[(nxt * B_TOT + s0 + es) * 16 + ed];
            }
        }
        if (tid < 16) {
            float wst = (st == 1 || st == 2) ? 3.f : 1.f;
            int gq = tid >> 2, si = tid & 3;
            float tr = shTW[(3 * gq) * 4 + si] + shTW[(3 * gq + 1) * 4 + si]
                     + shTW[(3 * gq + 2) * 4 + si];
            shTR[tid] += wst * tr;
        }
        __syncthreads();   // A: shYE(idx+1) ready
    }

    // gather y (register-resident, distributed over d-threads) then reduce
    if (tid < 256) shYE[es * 36 + ed] = yReg;
    __syncthreads();
    if (tid < 16) {
        float ss = 0.f;
        #pragma unroll
        for (int d = 0; d < 16; d++) { float v = shYE[tid * 36 + d]; ss += v * v; }
        out[s0 + tid] = -0.5f * ss - 14.703016531274763f + dtf * 0.125f * shTR[tid];
    }
}

extern "C" void kernel_launch(void* const* d_in, const int* in_sizes, int n_in,
                              void* d_out, int out_size) {
    const float* theta = (const float*)d_in[0];
    const float* hg    = (const float*)d_in[1];
    const float* eps   = (const float*)d_in[2];
    const float* W1    = (const float*)d_in[3];
    const float* b1    = (const float*)d_in[4];
    const float* W2    = (const float*)d_in[5];
    const float* b2    = (const float*)d_in[6];
    const float* W3    = (const float*)d_in[7];
    const float* b3    = (const float*)d_in[8];
    float* out = (float*)d_out;

    cudaFuncSetAttribute(ConditionalCNF_27590869910221_kernel,
                         cudaFuncAttributeMaxDynamicSharedMemorySize,
                         SMEM_FLOATS * (int)sizeof(float));
    ConditionalCNF_27590869910221_kernel<<<B_TOT / TM, NTHR,
                                           SMEM_FLOATS * sizeof(float)>>>(
        theta, hg, eps, W1, b1, W2, b2, W3, b3, out);
}

// round 15
// speedup vs baseline: 1.5586x; 1.5586x over previous
#include <cuda_runtime.h>

#define B_TOT   16384
#define TM      16
#define NTHR    384

typedef unsigned long long u64;

__device__ __forceinline__ u64 pk2(float lo, float hi) {
    u64 r; asm("mov.b64 %0,{%1,%2};" : "=l"(r) : "f"(lo), "f"(hi)); return r;
}
__device__ __forceinline__ float2 upk2(u64 v) {
    float2 f; asm("mov.b64 {%0,%1},%2;" : "=f"(f.x), "=f"(f.y) : "l"(v)); return f;
}
__device__ __forceinline__ void fma2(u64& d, u64 a, u64 b) {
    asm("fma.rn.f32x2 %0,%1,%2,%0;" : "+l"(d) : "l"(a), "l"(b));
}
__device__ __forceinline__ void add2(u64& d, u64 a) {
    asm("add.rn.f32x2 %0,%0,%1;" : "+l"(d) : "l"(a));
}
// pack two f32 -> bf16x2 (hi<<16 | lo)
__device__ __forceinline__ unsigned cvtb2(float hi, float lo) {
    unsigned r; asm("cvt.rn.bf16x2.f32 %0,%1,%2;" : "=r"(r) : "f"(hi), "f"(lo)); return r;
}
// unpack bf16x2 -> f32x2  (f32 = bf16 << 16)
__device__ __forceinline__ u64 bup(unsigned v) {
    unsigned lo = v << 16, hi = v & 0xFFFF0000u;
    u64 r; asm("mov.b64 %0,{%1,%2};" : "=l"(r) : "r"(lo), "r"(hi)); return r;
}

// Shared layout (floats):
//   [0,36864)        shW2   192x192 fp32
//   [36864,40704)    shAct  192x20  rows: 4 groups x uint4{a01,a23,d01,d23} bf16x2
//   [40704,43776)    shW1a  16x192
//   [43776,46848)    shW3t  16x192
//   [46848,46864)    shB3   16
//   [46864,...)      ALIAS P: prologue hS 256x16 (4096) overlays:
//     P+0     shA2t  16x196 (3136)
//     P+3136  shFJ3  3x(16x17) (816)
//     P+3952  shTW   12x4 (48)
//     P+4000  shTR   16
//     P+4016  shYE   16x36 (576)
#define SMEM_FLOATS 51456

__global__ __launch_bounds__(NTHR, 1)
void ConditionalCNF_27590869910221_kernel(
    const float* __restrict__ theta, const float* __restrict__ hg,
    const float* __restrict__ eps,   const float* __restrict__ W1,
    const float* __restrict__ b1,    const float* __restrict__ W2,
    const float* __restrict__ b2,    const float* __restrict__ W3,
    const float* __restrict__ b3,    float* __restrict__ out)
{
    extern __shared__ float sm[];
    float* shW2  = sm;
    float* shAct = sm + 36864;
    float* shW1a = sm + 40704;
    float* shW3t = sm + 43776;
    float* shB3  = sm + 46848;
    float* hP    = sm + 46864;          // prologue alias base
    float* shA2t = sm + 46864;
    float* shFJ3 = sm + 50000;
    float* shTW  = sm + 50816;
    float* shTR  = sm + 50864;
    float* shYE  = sm + 50880;

    const int tid = threadIdx.x;
    const int u = tid % 96;          // column-pair index
    const int g = tid / 96;          // sample quartet (0..3)
    const int wid = tid >> 5;        // warp id (uniform g per warp)
    const int lane = tid & 31;
    const int j0 = 2 * u;
    const int sb = 4 * g;            // sample base within tile
    const int s0 = blockIdx.x * TM;
    const float dtf = -0.1f;
    const int es = tid >> 4, ed = tid & 15;   // slot (sample, dim) for tid<256

    // per-thread constants
    const float2 w1tReg = *(const float2*)(W1 + 272 * 192 + j0);
    const float2 b2Reg  = *(const float2*)(b2 + j0);

    // ---------------- phase 0: stage weights / state ----------------
    float yReg = 0.f, fb1 = 0.f, fb2 = 0.f, fb3 = 0.f, epsReg = 0.f;
    {
        const float4* W2g4 = (const float4*)W2;
        float4* shW24 = (float4*)shW2;
        for (int i = tid; i < 36864 / 4; i += NTHR) shW24[i] = W2g4[i];
        for (int i = tid; i < 3072; i += NTHR) shW1a[i] = W1[i];           // rows 0..15
        for (int i = tid; i < 3072; i += NTHR) {                           // W3 transpose
            int k = i >> 4, dd = i & 15;
            shW3t[dd * 192 + k] = W3[i];
        }
        if (tid < 16) shB3[tid] = b3[tid];
        if (tid < 256) {
            yReg = theta[s0 * 16 + tid];
            epsReg = eps[(0 * B_TOT + s0 + es) * 16 + ed];
        }
        // h tile into hP as hS[c][s], row stride 16 (prologue alias)
        const float4* hg4 = (const float4*)hg;
        for (int i = tid; i < 1024; i += NTHR) {
            float4 v = hg4[s0 * 64 + i];
            int s = i >> 6, c = (i & 63) * 4;
            hP[(c + 0) * 16 + s] = v.x; hP[(c + 1) * 16 + s] = v.y;
            hP[(c + 2) * 16 + s] = v.z; hP[(c + 3) * 16 + s] = v.w;
        }
    }
    __syncthreads();

    // ------------- hc = b1 + h @ W1[16:272,:] (register resident) -------------
    u64 hcReg[2][2];
    {
        float2 bj = *(const float2*)(b1 + j0);
        hcReg[0][0] = hcReg[0][1] = pk2(bj.x, bj.x);
        hcReg[1][0] = hcReg[1][1] = pk2(bj.y, bj.y);
        const float* hrow = hP + sb;
        #pragma unroll 4
        for (int k = 0; k < 256; k++) {
            float2 w = *(const float2*)(W1 + (16 + k) * 192 + j0);         // L2-resident LDG
            u64 w0 = pk2(w.x, w.x), w1 = pk2(w.y, w.y);
            ulonglong2 A0 = *(const ulonglong2*)(hrow + k * 16);
            fma2(hcReg[0][0], A0.x, w0); fma2(hcReg[0][1], A0.y, w0);
            fma2(hcReg[1][0], A0.x, w1); fma2(hcReg[1][1], A0.y, w1);
        }
    }
    __syncthreads();   // all hS reads done; alias region reusable

    // shYE init for stage 0 (y = theta, eps[0]); prefetch eps[1]; shTR zero
    if (tid < 256) {
        shYE[ed * 36 + es] = yReg;
        shYE[ed * 36 + 16 + es] = epsReg;
        epsReg = eps[(1 * B_TOT + s0 + es) * 16 + ed];
    }
    if (tid < 16) shTR[tid] = 0.f;
    __syncthreads();   // shYE(0) ready

    const float kSQ = 0.70710678118654752f;    // 1/sqrt(2)
    const float kPDF = 0.3989422804014327f;    // 1/sqrt(2*pi)

    u64 aA[2][2], aD[2][2], aW[2][2];

    for (int idx = 0; idx < 40; idx++) {
        int st = idx & 3;
        float t0 = 1.0f + dtf * (float)(idx >> 2);
        float tc = t0 + dtf * (st == 0 ? 0.f : st == 1 ? (1.f / 3.f)
                             : st == 2 ? (2.f / 3.f) : 1.f);

        // ---- layer 1: z1 = hc + t*W1t + y@W1a ; dz1 = e@W1a ; we = W3.e ----
        {
            u64 tw0 = pk2(tc * w1tReg.x, tc * w1tReg.x);
            u64 tw1 = pk2(tc * w1tReg.y, tc * w1tReg.y);
            #pragma unroll
            for (int p = 0; p < 2; p++) {
                aA[0][p] = hcReg[0][p]; add2(aA[0][p], tw0);
                aA[1][p] = hcReg[1][p]; add2(aA[1][p], tw1);
                aD[0][p] = aD[1][p] = 0ull;
                aW[0][p] = aW[1][p] = 0ull;
            }
        }
        #pragma unroll
        for (int k = 0; k < 16; k++) {
            const float* ar = shYE + k * 36 + sb;
            ulonglong2 A0 = *(const ulonglong2*)ar;
            ulonglong2 E0 = *(const ulonglong2*)(ar + 16);
            float2 w  = *(const float2*)(shW1a + k * 192 + j0);
            float2 w3 = *(const float2*)(shW3t + k * 192 + j0);
            u64 w0 = pk2(w.x, w.x), w1 = pk2(w.y, w.y);
            u64 v0 = pk2(w3.x, w3.x), v1 = pk2(w3.y, w3.y);
            fma2(aA[0][0], A0.x, w0); fma2(aA[0][1], A0.y, w0);
            fma2(aA[1][0], A0.x, w1); fma2(aA[1][1], A0.y, w1);
            fma2(aD[0][0], E0.x, w0); fma2(aD[0][1], E0.y, w0);
            fma2(aD[1][0], E0.x, w1); fma2(aD[1][1], E0.y, w1);
            fma2(aW[0][0], E0.x, v0); fma2(aW[0][1], E0.y, v0);
            fma2(aW[1][0], E0.x, v1); fma2(aW[1][1], E0.y, v1);
        }

        // GELU layer1 + store a1/d1 packed bf16: uint4{a01,a23,d01,d23}
        #pragma unroll
        for (int jj = 0; jj < 2; jj++) {
            float va[4], vd[4];
            #pragma unroll
            for (int p = 0; p < 2; p++) {
                float2 z  = upk2(aA[jj][p]);
                float2 dz = upk2(aD[jj][p]);
                float c0 = 0.5f * (1.f + erff(z.x * kSQ));
                float c1 = 0.5f * (1.f + erff(z.y * kSQ));
                va[2 * p]     = z.x * c0;
                va[2 * p + 1] = z.y * c1;
                float g0 = c0 + z.x * kPDF * __expf(-0.5f * z.x * z.x);
                float g1 = c1 + z.y * kPDF * __expf(-0.5f * z.y * z.y);
                vd[2 * p]     = g0 * dz.x;
                vd[2 * p + 1] = g1 * dz.y;
            }
            uint4 pkd;
            pkd.x = cvtb2(va[1], va[0]); pkd.y = cvtb2(va[3], va[2]);
            pkd.z = cvtb2(vd[1], vd[0]); pkd.w = cvtb2(vd[3], vd[2]);
            *(uint4*)(shAct + (j0 + jj) * 20 + sb) = pkd;
        }
        __syncthreads();   // B: act rows ready

        // ---- layer 2: z2 = a1@W2 + b2 ; dz2 = d1@W2 (bf16 acts, fp32 weights) ----
        #pragma unroll
        for (int p = 0; p < 2; p++) {
            aA[0][p] = pk2(b2Reg.x, b2Reg.x);
            aA[1][p] = pk2(b2Reg.y, b2Reg.y);
            aD[0][p] = aD[1][p] = 0ull;
        }
        #pragma unroll 8
        for (int k = 0; k < 192; k++) {
            uint4 q = *(const uint4*)(shAct + k * 20 + sb);
            float2 w = *(const float2*)(shW2 + k * 192 + j0);
            u64 w0 = pk2(w.x, w.x), w1 = pk2(w.y, w.y);
            u64 A0 = bup(q.x), A1 = bup(q.y);
            u64 E0 = bup(q.z), E1 = bup(q.w);
            fma2(aA[0][0], A0, w0); fma2(aA[0][1], A1, w0);
            fma2(aA[1][0], A0, w1); fma2(aA[1][1], A1, w1);
            fma2(aD[0][0], E0, w0); fma2(aD[0][1], E1, w0);
            fma2(aD[1][0], E0, w1); fma2(aD[1][1], E1, w1);
        }

        // GELU layer2: a2 -> shA2t fp32 (own region); trace partial in regs
        float tp[4] = {0.f, 0.f, 0.f, 0.f};
        #pragma unroll
        for (int jj = 0; jj < 2; jj++) {
            #pragma unroll
            for (int p = 0; p < 2; p++) {
                float2 z  = upk2(aA[jj][p]);
                float2 dz = upk2(aD[jj][p]);
                float c0 = 0.5f * (1.f + erff(z.x * kSQ));
                float c1 = 0.5f * (1.f + erff(z.y * kSQ));
                float a0 = z.x * c0, a1v = z.y * c1;
                float g0 = c0 + z.x * kPDF * __expf(-0.5f * z.x * z.x);
                float g1 = c1 + z.y * kPDF * __expf(-0.5f * z.y * z.y);
                float d0 = g0 * dz.x, d1v = g1 * dz.y;
                int ca = sb + 2 * p;
                shA2t[(ca)     * 196 + j0 + jj] = a0;
                shA2t[(ca + 1) * 196 + j0 + jj] = a1v;
                float2 wv = upk2(aW[jj][p]);
                tp[2 * p]     += d0  * wv.x;     // d2 . (W3 e)
                tp[2 * p + 1] += d1v * wv.y;
            }
        }
        // warp butterfly reduce (warp uniform in g)
        #pragma unroll
        for (int off = 16; off > 0; off >>= 1) {
            #pragma unroll
            for (int i = 0; i < 4; i++)
                tp[i] += __shfl_xor_sync(0xFFFFFFFFu, tp[i], off);
        }
        if (lane == 0) {
            #pragma unroll
            for (int i = 0; i < 4; i++) shTW[wid * 4 + i] = tp[i];
        }
        __syncthreads();   // D: a2t + shTW ready

        // ---- layer 3: f = a2 @ W3, 3-way K-split, 768 microtasks over 384 thr ----
        #pragma unroll
        for (int r = 0; r < 2; r++) {
            int m = tid + 384 * r;
            int third = m >> 8, o = m & 255;
            int s = o & 15, dd = o >> 4;
            const float* ap = shA2t + s * 196 + third * 64;
            const float* wp = shW3t + dd * 192 + third * 64;
            float acc = 0.f;
            #pragma unroll 8
            for (int k = 0; k < 64; k += 4) {
                float4 av = *(const float4*)(ap + k);
                float4 wv = *(const float4*)(wp + k);
                acc += av.x * wv.x + av.y * wv.y + av.z * wv.z + av.w * wv.w;
            }
            shFJ3[third * 272 + s * 17 + dd] = acc;
        }
        __syncthreads();   // E: shFJ3 ready

        // ---- fused epilogue + next-stage staging ----
        if (tid < 256) {
            float f = shFJ3[es * 17 + ed] + shFJ3[272 + es * 17 + ed]
                    + shFJ3[544 + es * 17 + ed] + shB3[ed];
            float yc;
            if      (st == 0) { fb1 = f; yc = yReg + (dtf * (1.f / 3.f)) * fb1; }
            else if (st == 1) { fb2 = f; yc = yReg + dtf * (fb2 - (1.f / 3.f) * fb1); }
            else if (st == 2) { fb3 = f; yc = yReg + dtf * (fb1 - fb2 + fb3); }
            else { yReg += dtf * 0.125f * (fb1 + 3.f * (fb2 + fb3) + f); yc = yReg; }
            if (idx < 39) {
                shYE[ed * 36 + es] = yc;
                shYE[ed * 36 + 16 + es] = epsReg;       // eps for stage idx+1
                int nxt = idx + 2; if (nxt > 39) nxt = 39;
                epsReg = eps[(nxt * B_TOT + s0 + es) * 16 + ed];
            }
        }
        if (tid < 16) {
            float wst = (st == 1 || st == 2) ? 3.f : 1.f;
            int gq = tid >> 2, si = tid & 3;
            float tr = shTW[(3 * gq) * 4 + si] + shTW[(3 * gq + 1) * 4 + si]
                     + shTW[(3 * gq + 2) * 4 + si];
            shTR[tid] += wst * tr;
        }
        __syncthreads();   // A: shYE(idx+1) ready
    }

    // gather y (register-resident, distributed over d-threads) then reduce
    if (tid < 256) shYE[es * 36 + ed] = yReg;
    __syncthreads();
    if (tid < 16) {
        float ss = 0.f;
        #pragma unroll
        for (int d = 0; d < 16; d++) { float v = shYE[tid * 36 + d]; ss += v * v; }
        out[s0 + tid] = -0.5f * ss - 14.703016531274763f + dtf * 0.125f * shTR[tid];
    }
}

extern "C" void kernel_launch(void* const* d_in, const int* in_sizes, int n_in,
                              void* d_out, int out_size) {
    const float* theta = (const float*)d_in[0];
    const float* hg    = (const float*)d_in[1];
    const float* eps   = (const float*)d_in[2];
    const float* W1    = (const float*)d_in[3];
    const float* b1    = (const float*)d_in[4];
    const float* W2    = (const float*)d_in[5];
    const float* b2    = (const float*)d_in[6];
    const float* W3    = (const float*)d_in[7];
    const float* b3    = (const float*)d_in[8];
    float* out = (float*)d_out;

    cudaFuncSetAttribute(ConditionalCNF_27590869910221_kernel,
                         cudaFuncAttributeMaxDynamicSharedMemorySize,
                         SMEM_FLOATS * (int)sizeof(float));
    ConditionalCNF_27590869910221_kernel<<<B_TOT / TM, NTHR,
                                           SMEM_FLOATS * sizeof(float)>>>(
        theta, hg, eps, W1, b1, W2, b2, W3, b3, out);
}